// round 15
// baseline (speedup 1.0000x reference)
#include <cuda_runtime.h>
#include <cuda_bf16.h>
#include <cstdint>

#define D 64
#define N_MAX 131072
#define E_MAX 2097152

// -------- device scratch --------
__device__ float g_H[N_MAX * D];    // post-GEMM features, pre-scaled by dinv[row]
__device__ float g_A[N_MAX * D];    // activations
__device__ int   g_cnt[N_MAX];      // statically zero; re-zeroed by k_scanA each run
__device__ float g_dinv[N_MAX];
__device__ int   g_rowtmp[N_MAX];
__device__ int   g_rowptr[N_MAX + 1];
__device__ int   g_cursor[N_MAX];   // seeded to rowptr by k_scanC each run
__device__ int   g_part[256];
__device__ int   g_col[E_MAX];      // src index only (4B payload)

__device__ __forceinline__ float tf32f(float f) {
    uint32_t r;
    asm("cvt.rna.tf32.f32 %0, %1;" : "=r"(r) : "f"(f));
    return __uint_as_float(r);
}

// per-block edge dtype probe: int64 buffer (values < 2^31) has zero odd slots
__device__ __forceinline__ int probe_elw(const int* __restrict__ p) {
    int nz = 0;
#pragma unroll
    for (int k = 0; k < 16; k++) nz |= p[2 * k + 1];
    return nz ? 1 : 2;
}

// -------- load helper: 8 edge endpoints at element offset ofs --------
__device__ __forceinline__ void load8(const int* __restrict__ p, long long ofs,
                                      int avail, int elw, int* v) {
    if (elw == 1) {
        if (avail == 8 && ((ofs & 3) == 0)) {
            int4 a = *(const int4*)(p + ofs);
            int4 b = *(const int4*)(p + ofs + 4);
            v[0]=a.x; v[1]=a.y; v[2]=a.z; v[3]=a.w;
            v[4]=b.x; v[5]=b.y; v[6]=b.z; v[7]=b.w;
        } else {
            for (int i = 0; i < 8; i++) v[i] = (i < avail) ? p[ofs + i] : -1;
        }
    } else {
        const long long* q = (const long long*)p;
        if (avail == 8 && ((ofs & 1) == 0)) {
            longlong2 a = *(const longlong2*)(q + ofs);
            longlong2 b = *(const longlong2*)(q + ofs + 2);
            longlong2 c = *(const longlong2*)(q + ofs + 4);
            longlong2 d = *(const longlong2*)(q + ofs + 6);
            v[0]=(int)a.x; v[1]=(int)a.y; v[2]=(int)b.x; v[3]=(int)b.y;
            v[4]=(int)c.x; v[5]=(int)c.y; v[6]=(int)d.x; v[7]=(int)d.y;
        } else {
            for (int i = 0; i < 8; i++) v[i] = (i < avail) ? (int)q[ofs + i] : -1;
        }
    }
}

// -------- degree count: 8 edges/thread, REDG (no return) --------
__global__ void __launch_bounds__(512) k_count(const int* __restrict__ p, int e, int n) {
    __shared__ int selw;
    if (threadIdx.x == 0) selw = probe_elw(p);
    __syncthreads();
    int elw = selw;
    int base = (blockIdx.x * blockDim.x + threadIdx.x) * 8;
    if (base >= e) return;
    int avail = min(8, e - base);
    int d[8];
    load8(p, (long long)e + base, avail, elw, d);
#pragma unroll
    for (int i = 0; i < 8; i++)
        if ((unsigned)d[i] < (unsigned)n) atomicAdd(&g_cnt[d[i]], 1);
}

// -------- scan A: warp-shuffle block scan + dinv + cnt reset --------
__global__ void __launch_bounds__(1024) k_scanA(int n) {
    __shared__ int wsum[32];
    int i = blockIdx.x * 1024 + threadIdx.x;
    int v = (i < n) ? g_cnt[i] : 0;
    if (i < n) {
        g_dinv[i] = rsqrtf((float)(v + 1));
        g_cnt[i] = 0;   // reset for next graph replay
    }
    int lane = threadIdx.x & 31, w = threadIdx.x >> 5;

    int x = v;
#pragma unroll
    for (int off = 1; off < 32; off <<= 1) {
        int t = __shfl_up_sync(0xffffffffu, x, off);
        if (lane >= off) x += t;
    }
    if (lane == 31) wsum[w] = x;
    __syncthreads();
    if (w == 0) {
        int s = wsum[lane];
        int t = s;
#pragma unroll
        for (int off = 1; off < 32; off <<= 1) {
            int u = __shfl_up_sync(0xffffffffu, t, off);
            if (lane >= off) t += u;
        }
        wsum[lane] = t - s;
        if (lane == 31) g_part[blockIdx.x] = t;
    }
    __syncthreads();
    if (i < n) g_rowtmp[i] = x - v + wsum[w];
}

// -------- scan C: local scan of partials; writes rowptr AND cursor --------
__global__ void k_scanC(int n, int e, int nb) {
    __shared__ int sh[128];
    __shared__ int ex[128];
    int t = threadIdx.x & 127;
    int v = (t < nb) ? g_part[t] : 0;
    sh[t] = v;
    __syncthreads();
#pragma unroll
    for (int off = 1; off < 128; off <<= 1) {
        int u = (t >= off) ? sh[t - off] : 0;
        __syncthreads();
        sh[t] += u;
        __syncthreads();
    }
    ex[t] = sh[t] - v;
    __syncthreads();

    int i = blockIdx.x * blockDim.x + threadIdx.x;
    if (i < n) {
        int rp = g_rowtmp[i] + ex[i >> 10];
        g_rowptr[i] = rp;
        g_cursor[i] = rp;
    }
    if (i == 0) g_rowptr[n] = e;
}

// -------- CSR fill: 8 edges/thread; single atomic per edge; 4B payload --------
__global__ void __launch_bounds__(512) k_fill(const int* __restrict__ p, int e, int n) {
    __shared__ int selw;
    if (threadIdx.x == 0) selw = probe_elw(p);
    __syncthreads();
    int elw = selw;
    int base = (blockIdx.x * blockDim.x + threadIdx.x) * 8;
    if (base >= e) return;
    int avail = min(8, e - base);
    int s[8], d[8];
    load8(p, (long long)base, avail, elw, s);
    load8(p, (long long)e + base, avail, elw, d);

    int pos[8];
#pragma unroll
    for (int i = 0; i < 8; i++) {
        pos[i] = -1;
        if ((unsigned)s[i] < (unsigned)n && (unsigned)d[i] < (unsigned)n)
            pos[i] = atomicAdd(&g_cursor[d[i]], 1);
    }
#pragma unroll
    for (int i = 0; i < 8; i++)
        if (pos[i] >= 0) g_col[pos[i]] = s[i];
}

// -------- GEMM: g_H[r,:] = dinv[r] * (A[r,:] @ W) via tf32 mma.sync --------
template <int SRC>
__global__ void __launch_bounds__(128) k_gemm(const float* __restrict__ Aext,
                                              const float* __restrict__ W, int n) {
    __shared__ float As[64][68];
    __shared__ float Ws[64][72];

    const float* A = (SRC == 0) ? Aext : (const float*)g_A;
    int tid = threadIdx.x;
    int rowbase = blockIdx.x * 64;

#pragma unroll
    for (int i = 0; i < 8; i++) {
        int idx = tid + i * 128;
        int r = idx >> 4, f4 = idx & 15;
        float4 va = (rowbase + r < n)
            ? *(const float4*)(A + (size_t)(rowbase + r) * 64 + f4 * 4)
            : make_float4(0.f, 0.f, 0.f, 0.f);
        As[r][f4 * 4 + 0] = tf32f(va.x); As[r][f4 * 4 + 1] = tf32f(va.y);
        As[r][f4 * 4 + 2] = tf32f(va.z); As[r][f4 * 4 + 3] = tf32f(va.w);
        float4 vw = *(const float4*)(W + r * 64 + f4 * 4);
        Ws[r][f4 * 4 + 0] = tf32f(vw.x); Ws[r][f4 * 4 + 1] = tf32f(vw.y);
        Ws[r][f4 * 4 + 2] = tf32f(vw.z); Ws[r][f4 * 4 + 3] = tf32f(vw.w);
    }
    __syncthreads();

    int warp = tid >> 5, lane = tid & 31;
    int gid = lane >> 2, tig = lane & 3;
    int ar0 = warp * 16 + gid, ar1 = ar0 + 8;

    float acc[8][4];
#pragma unroll
    for (int t = 0; t < 8; t++)
#pragma unroll
        for (int c = 0; c < 4; c++) acc[t][c] = 0.f;

#pragma unroll
    for (int ks = 0; ks < 8; ks++) {
        int k0 = ks * 8;
        uint32_t a0 = __float_as_uint(As[ar0][k0 + tig]);
        uint32_t a1 = __float_as_uint(As[ar1][k0 + tig]);
        uint32_t a2 = __float_as_uint(As[ar0][k0 + tig + 4]);
        uint32_t a3 = __float_as_uint(As[ar1][k0 + tig + 4]);
#pragma unroll
        for (int nt = 0; nt < 8; nt++) {
            uint32_t b0 = __float_as_uint(Ws[k0 + tig][nt * 8 + gid]);
            uint32_t b1 = __float_as_uint(Ws[k0 + tig + 4][nt * 8 + gid]);
            asm volatile(
                "mma.sync.aligned.m16n8k8.row.col.f32.tf32.tf32.f32 "
                "{%0,%1,%2,%3}, {%4,%5,%6,%7}, {%8,%9}, {%0,%1,%2,%3};"
                : "+f"(acc[nt][0]), "+f"(acc[nt][1]), "+f"(acc[nt][2]), "+f"(acc[nt][3])
                : "r"(a0), "r"(a1), "r"(a2), "r"(a3), "r"(b0), "r"(b1));
        }
    }

    int row0 = rowbase + warp * 16 + gid, row1 = row0 + 8;
    float s0 = (row0 < n) ? g_dinv[row0] : 0.f;
    float s1 = (row1 < n) ? g_dinv[row1] : 0.f;
#pragma unroll
    for (int nt = 0; nt < 8; nt++) {
        int col = nt * 8 + tig * 2;
        if (row0 < n)
            *(float2*)(g_H + (size_t)row0 * 64 + col) =
                make_float2(acc[nt][0] * s0, acc[nt][1] * s0);
        if (row1 < n)
            *(float2*)(g_H + (size_t)row1 * 64 + col) =
                make_float2(acc[nt][2] * s1, acc[nt][3] * s1);
    }
}

// -------- Aggregation: acc = H'[i] + sum_j H'[src_j]; out = relu(di*acc + b) --------
template <int DSTOUT>
__global__ void k_agg(const float* __restrict__ bias, float* __restrict__ outext,
                      int n) {
    int gw = (blockIdx.x * blockDim.x + threadIdx.x) >> 5;
    int lane = threadIdx.x & 31;
    if (gw >= n) return;
    int i = gw;

    const float2* H2 = (const float2*)g_H;
    float di = g_dinv[i];
    float2 acc = H2[i * 32 + lane];   // self term: H'_i = dinv_i * H_i (pre-scaled)

    int s = g_rowptr[i], e = g_rowptr[i + 1];
    for (int base = s; base < e; base += 32) {
        int m = min(32, e - base);
        int c = (lane < m) ? g_col[base + lane] : 0;
#pragma unroll 4
        for (int j = 0; j < m; j++) {
            int cj = __shfl_sync(0xffffffffu, c, j);
            float2 hh = __ldg(&H2[cj * 32 + lane]);
            acc.x += hh.x;
            acc.y += hh.y;
        }
    }
    float2 bb = ((const float2*)bias)[lane];
    acc.x = fmaxf(acc.x * di + bb.x, 0.f);
    acc.y = fmaxf(acc.y * di + bb.y, 0.f);
    float2* outp = (DSTOUT == 0) ? (float2*)g_A : (float2*)outext;
    outp[i * 32 + lane] = acc;
}

// -------- launch: single stream, fully serial --------
extern "C" void kernel_launch(void* const* d_in, const int* in_sizes, int n_in,
                              void* d_out, int out_size) {
    const float* x  = (const float*)d_in[0];
    const int*   ei = (const int*)d_in[1];
    const float* W0 = (const float*)d_in[2];
    const float* b0 = (const float*)d_in[3];
    const float* W1 = (const float*)d_in[4];
    const float* b1 = (const float*)d_in[5];
    const float* W2 = (const float*)d_in[6];
    const float* b2 = (const float*)d_in[7];
    float* out = (float*)d_out;

    int n = in_sizes[0] / D;
    int e = in_sizes[1] / 2;
    int nb = (n + 1023) / 1024;
    int e8 = (e + 7) / 8;

    int tile_blocks = (n + 63) / 64;
    int agg_blocks  = (n + 7) / 8;

    k_count<<<(e8 + 511) / 512, 512>>>(ei, e, n);
    k_scanA<<<nb, 1024>>>(n);
    k_scanC<<<(n + 255) / 256, 256>>>(n, e, nb);
    k_fill <<<(e8 + 511) / 512, 512>>>(ei, e, n);

    k_gemm<0><<<tile_blocks, 128>>>(x, W0, n);
    k_agg<0> <<<agg_blocks, 256>>>(b0, nullptr, n);
    k_gemm<1><<<tile_blocks, 128>>>(nullptr, W1, n);
    k_agg<0> <<<agg_blocks, 256>>>(b1, nullptr, n);
    k_gemm<1><<<tile_blocks, 128>>>(nullptr, W2, n);
    k_agg<1> <<<agg_blocks, 256>>>(b2, out, n);
}

// round 16
// speedup vs baseline: 1.0024x; 1.0024x over previous
#include <cuda_runtime.h>
#include <cuda_bf16.h>
#include <cstdint>

#define D 64
#define N_MAX 131072
#define E_MAX 2097152

// -------- device scratch --------
__device__ float g_H[N_MAX * D];    // post-GEMM features, pre-scaled by dinv[row]
__device__ float g_A[N_MAX * D];    // activations
__device__ int   g_cnt[N_MAX];      // degree; reset by final agg each run
__device__ float g_dinv[N_MAX];
__device__ int   g_rowstart[N_MAX]; // CSR region start (arbitrary global order)
__device__ int   g_cursor[N_MAX];   // seeded to rowstart by k_scan each run
__device__ int   g_total;           // region allocator; reset by final agg
__device__ int   g_col[E_MAX];      // src index only (4B payload)

__device__ __forceinline__ float tf32f(float f) {
    uint32_t r;
    asm("cvt.rna.tf32.f32 %0, %1;" : "=r"(r) : "f"(f));
    return __uint_as_float(r);
}

// per-block edge dtype probe: int64 buffer (values < 2^31) has zero odd slots
__device__ __forceinline__ int probe_elw(const int* __restrict__ p) {
    int nz = 0;
#pragma unroll
    for (int k = 0; k < 16; k++) nz |= p[2 * k + 1];
    return nz ? 1 : 2;
}

// -------- load helper: 8 edge endpoints at element offset ofs --------
__device__ __forceinline__ void load8(const int* __restrict__ p, long long ofs,
                                      int avail, int elw, int* v) {
    if (elw == 1) {
        if (avail == 8 && ((ofs & 3) == 0)) {
            int4 a = *(const int4*)(p + ofs);
            int4 b = *(const int4*)(p + ofs + 4);
            v[0]=a.x; v[1]=a.y; v[2]=a.z; v[3]=a.w;
            v[4]=b.x; v[5]=b.y; v[6]=b.z; v[7]=b.w;
        } else {
            for (int i = 0; i < 8; i++) v[i] = (i < avail) ? p[ofs + i] : -1;
        }
    } else {
        const long long* q = (const long long*)p;
        if (avail == 8 && ((ofs & 1) == 0)) {
            longlong2 a = *(const longlong2*)(q + ofs);
            longlong2 b = *(const longlong2*)(q + ofs + 2);
            longlong2 c = *(const longlong2*)(q + ofs + 4);
            longlong2 d = *(const longlong2*)(q + ofs + 6);
            v[0]=(int)a.x; v[1]=(int)a.y; v[2]=(int)b.x; v[3]=(int)b.y;
            v[4]=(int)c.x; v[5]=(int)c.y; v[6]=(int)d.x; v[7]=(int)d.y;
        } else {
            for (int i = 0; i < 8; i++) v[i] = (i < avail) ? (int)q[ofs + i] : -1;
        }
    }
}

// -------- degree count: 8 edges/thread, REDG (no return) --------
__global__ void __launch_bounds__(512) k_count(const int* __restrict__ p, int e, int n) {
    __shared__ int selw;
    if (threadIdx.x == 0) selw = probe_elw(p);
    __syncthreads();
    int elw = selw;
    int base = (blockIdx.x * blockDim.x + threadIdx.x) * 8;
    if (base >= e) return;
    int avail = min(8, e - base);
    int d[8];
    load8(p, (long long)e + base, avail, elw, d);
#pragma unroll
    for (int i = 0; i < 8; i++)
        if ((unsigned)d[i] < (unsigned)n) atomicAdd(&g_cnt[d[i]], 1);
}

// -------- merged scan: per-block local scan + one atomic region claim --------
// Rows placed in arbitrary block order; [rowstart, rowstart+cnt) is consistent.
__global__ void __launch_bounds__(1024) k_scan(int n) {
    __shared__ int wsum[32];
    __shared__ int sbase;
    int i = blockIdx.x * 1024 + threadIdx.x;
    int v = (i < n) ? g_cnt[i] : 0;
    if (i < n) g_dinv[i] = rsqrtf((float)(v + 1));
    int lane = threadIdx.x & 31, w = threadIdx.x >> 5;

    int x = v;  // inclusive warp scan
#pragma unroll
    for (int off = 1; off < 32; off <<= 1) {
        int t = __shfl_up_sync(0xffffffffu, x, off);
        if (lane >= off) x += t;
    }
    if (lane == 31) wsum[w] = x;
    __syncthreads();
    if (w == 0) {
        int s = wsum[lane];
        int t = s;
#pragma unroll
        for (int off = 1; off < 32; off <<= 1) {
            int u = __shfl_up_sync(0xffffffffu, t, off);
            if (lane >= off) t += u;
        }
        wsum[lane] = t - s;              // exclusive warp offsets
        if (lane == 31) sbase = atomicAdd(&g_total, t);  // claim block region
    }
    __syncthreads();
    if (i < n) {
        int rs = sbase + x - v + wsum[w];
        g_rowstart[i] = rs;
        g_cursor[i] = rs;
    }
}

// -------- CSR fill: 8 edges/thread; single atomic per edge; 4B payload --------
__global__ void __launch_bounds__(512) k_fill(const int* __restrict__ p, int e, int n) {
    __shared__ int selw;
    if (threadIdx.x == 0) selw = probe_elw(p);
    __syncthreads();
    int elw = selw;
    int base = (blockIdx.x * blockDim.x + threadIdx.x) * 8;
    if (base >= e) return;
    int avail = min(8, e - base);
    int s[8], d[8];
    load8(p, (long long)base, avail, elw, s);
    load8(p, (long long)e + base, avail, elw, d);

    int pos[8];
#pragma unroll
    for (int i = 0; i < 8; i++) {
        pos[i] = -1;
        if ((unsigned)s[i] < (unsigned)n && (unsigned)d[i] < (unsigned)n)
            pos[i] = atomicAdd(&g_cursor[d[i]], 1);
    }
#pragma unroll
    for (int i = 0; i < 8; i++)
        if (pos[i] >= 0) g_col[pos[i]] = s[i];
}

// -------- GEMM: g_H[r,:] = dinv[r] * (A[r,:] @ W) via tf32 mma.sync --------
template <int SRC>
__global__ void __launch_bounds__(128) k_gemm(const float* __restrict__ Aext,
                                              const float* __restrict__ W, int n) {
    __shared__ float As[64][68];
    __shared__ float Ws[64][72];

    const float* A = (SRC == 0) ? Aext : (const float*)g_A;
    int tid = threadIdx.x;
    int rowbase = blockIdx.x * 64;

#pragma unroll
    for (int i = 0; i < 8; i++) {
        int idx = tid + i * 128;
        int r = idx >> 4, f4 = idx & 15;
        float4 va = (rowbase + r < n)
            ? *(const float4*)(A + (size_t)(rowbase + r) * 64 + f4 * 4)
            : make_float4(0.f, 0.f, 0.f, 0.f);
        As[r][f4 * 4 + 0] = tf32f(va.x); As[r][f4 * 4 + 1] = tf32f(va.y);
        As[r][f4 * 4 + 2] = tf32f(va.z); As[r][f4 * 4 + 3] = tf32f(va.w);
        float4 vw = *(const float4*)(W + r * 64 + f4 * 4);
        Ws[r][f4 * 4 + 0] = tf32f(vw.x); Ws[r][f4 * 4 + 1] = tf32f(vw.y);
        Ws[r][f4 * 4 + 2] = tf32f(vw.z); Ws[r][f4 * 4 + 3] = tf32f(vw.w);
    }
    __syncthreads();

    int warp = tid >> 5, lane = tid & 31;
    int gid = lane >> 2, tig = lane & 3;
    int ar0 = warp * 16 + gid, ar1 = ar0 + 8;

    float acc[8][4];
#pragma unroll
    for (int t = 0; t < 8; t++)
#pragma unroll
        for (int c = 0; c < 4; c++) acc[t][c] = 0.f;

#pragma unroll
    for (int ks = 0; ks < 8; ks++) {
        int k0 = ks * 8;
        uint32_t a0 = __float_as_uint(As[ar0][k0 + tig]);
        uint32_t a1 = __float_as_uint(As[ar1][k0 + tig]);
        uint32_t a2 = __float_as_uint(As[ar0][k0 + tig + 4]);
        uint32_t a3 = __float_as_uint(As[ar1][k0 + tig + 4]);
#pragma unroll
        for (int nt = 0; nt < 8; nt++) {
            uint32_t b0 = __float_as_uint(Ws[k0 + tig][nt * 8 + gid]);
            uint32_t b1 = __float_as_uint(Ws[k0 + tig + 4][nt * 8 + gid]);
            asm volatile(
                "mma.sync.aligned.m16n8k8.row.col.f32.tf32.tf32.f32 "
                "{%0,%1,%2,%3}, {%4,%5,%6,%7}, {%8,%9}, {%0,%1,%2,%3};"
                : "+f"(acc[nt][0]), "+f"(acc[nt][1]), "+f"(acc[nt][2]), "+f"(acc[nt][3])
                : "r"(a0), "r"(a1), "r"(a2), "r"(a3), "r"(b0), "r"(b1));
        }
    }

    int row0 = rowbase + warp * 16 + gid, row1 = row0 + 8;
    float s0 = (row0 < n) ? g_dinv[row0] : 0.f;
    float s1 = (row1 < n) ? g_dinv[row1] : 0.f;
#pragma unroll
    for (int nt = 0; nt < 8; nt++) {
        int col = nt * 8 + tig * 2;
        if (row0 < n)
            *(float2*)(g_H + (size_t)row0 * 64 + col) =
                make_float2(acc[nt][0] * s0, acc[nt][1] * s0);
        if (row1 < n)
            *(float2*)(g_H + (size_t)row1 * 64 + col) =
                make_float2(acc[nt][2] * s1, acc[nt][3] * s1);
    }
}

// -------- Aggregation: acc = H'[i] + sum_j H'[src_j]; out = relu(di*acc + b) --------
// DSTOUT==1 (final layer) also resets g_cnt and g_total for the next replay.
template <int DSTOUT>
__global__ void k_agg(const float* __restrict__ bias, float* __restrict__ outext,
                      int n) {
    int gw = (blockIdx.x * blockDim.x + threadIdx.x) >> 5;
    int lane = threadIdx.x & 31;
    if (gw >= n) return;
    int i = gw;

    const float2* H2 = (const float2*)g_H;
    float di = g_dinv[i];
    float2 acc = H2[i * 32 + lane];   // self term: H'_i = dinv_i * H_i (pre-scaled)

    int s = g_rowstart[i];
    int cnt = g_cnt[i];
    int e = s + cnt;
    for (int base = s; base < e; base += 32) {
        int m = min(32, e - base);
        int c = (lane < m) ? g_col[base + lane] : 0;
#pragma unroll 4
        for (int j = 0; j < m; j++) {
            int cj = __shfl_sync(0xffffffffu, c, j);
            float2 hh = __ldg(&H2[cj * 32 + lane]);
            acc.x += hh.x;
            acc.y += hh.y;
        }
    }
    float2 bb = ((const float2*)bias)[lane];
    acc.x = fmaxf(acc.x * di + bb.x, 0.f);
    acc.y = fmaxf(acc.y * di + bb.y, 0.f);
    float2* outp = (DSTOUT == 0) ? (float2*)g_A : (float2*)outext;
    outp[i * 32 + lane] = acc;

    if (DSTOUT == 1 && lane == 0) {
        g_cnt[i] = 0;                 // reset for next replay
        if (i == 0) g_total = 0;
    }
}

// -------- launch: single stream, fully serial --------
extern "C" void kernel_launch(void* const* d_in, const int* in_sizes, int n_in,
                              void* d_out, int out_size) {
    const float* x  = (const float*)d_in[0];
    const int*   ei = (const int*)d_in[1];
    const float* W0 = (const float*)d_in[2];
    const float* b0 = (const float*)d_in[3];
    const float* W1 = (const float*)d_in[4];
    const float* b1 = (const float*)d_in[5];
    const float* W2 = (const float*)d_in[6];
    const float* b2 = (const float*)d_in[7];
    float* out = (float*)d_out;

    int n = in_sizes[0] / D;
    int e = in_sizes[1] / 2;
    int nb = (n + 1023) / 1024;
    int e8 = (e + 7) / 8;

    int tile_blocks = (n + 63) / 64;
    int agg_blocks  = (n + 7) / 8;

    k_count<<<(e8 + 511) / 512, 512>>>(ei, e, n);
    k_scan <<<nb, 1024>>>(n);
    k_fill <<<(e8 + 511) / 512, 512>>>(ei, e, n);

    k_gemm<0><<<tile_blocks, 128>>>(x, W0, n);
    k_agg<0> <<<agg_blocks, 256>>>(b0, nullptr, n);
    k_gemm<1><<<tile_blocks, 128>>>(nullptr, W1, n);
    k_agg<0> <<<agg_blocks, 256>>>(b1, nullptr, n);
    k_gemm<1><<<tile_blocks, 128>>>(nullptr, W2, n);
    k_agg<1> <<<agg_blocks, 256>>>(b2, out, n);
}